// round 7
// baseline (speedup 1.0000x reference)
#include <cuda_runtime.h>
#include <cstdint>
#include <cstddef>
#include <math.h>

#define SEQ   100
#define BATCH 2048
#define HID   1024
#define VOC   42
#define NG    4096   // 4*HID
#define KP    48     // padded K for x / w_ih0 (42 -> 48, multiple of 16)

// ---------------- scratch (device globals; no allocation allowed) ----------------
__device__ __align__(256) float g_Whh0[NG * HID];
__device__ __align__(256) float g_Wih1[NG * HID];
__device__ __align__(256) float g_Whh1[NG * HID];
__device__ __align__(256) float g_Wih0[NG * KP];
__device__ __align__(256) float g_b0[NG];
__device__ __align__(256) float g_b1[NG];
__device__ __align__(256) float g_h0a[BATCH * HID];
__device__ __align__(256) float g_h0b[BATCH * HID];
__device__ __align__(256) float g_h1a[BATCH * HID];
__device__ __align__(256) float g_h1b[BATCH * HID];
__device__ __align__(256) float g_c0[BATCH * HID];
__device__ __align__(256) float g_c1[BATCH * HID];
__device__ __align__(256) float g_x[BATCH * KP];

// ---------------- small helpers ----------------
__device__ __forceinline__ unsigned f2tf(float f) {
    unsigned u;
    asm("cvt.rna.tf32.f32 %0, %1;" : "=r"(u) : "f"(f));
    return u;
}

__device__ __forceinline__ void mma8(float c[4],
                                     unsigned a0, unsigned a1, unsigned a2, unsigned a3,
                                     unsigned b0, unsigned b1) {
    asm volatile(
        "mma.sync.aligned.m16n8k8.row.col.f32.tf32.tf32.f32 "
        "{%0,%1,%2,%3}, {%4,%5,%6,%7}, {%8,%9}, {%0,%1,%2,%3};"
        : "+f"(c[0]), "+f"(c[1]), "+f"(c[2]), "+f"(c[3])
        : "r"(a0), "r"(a1), "r"(a2), "r"(a3), "r"(b0), "r"(b1));
}

__device__ __forceinline__ void cp16(float* dst, const float* src) {
    unsigned s = (unsigned)__cvta_generic_to_shared(dst);
    asm volatile("cp.async.cg.shared.global [%0], [%1], 16;\n" :: "r"(s), "l"(src) : "memory");
}

__device__ __forceinline__ float sigmoidf(float x) { return 1.0f / (1.0f + expf(-x)); }

// ---------------- prep kernels ----------------
// Interleave gate rows: dst[(4h+g)*K + k] = src[(g*HID + h)*K + k]. K divisible by 4.
__global__ void permute_w(const float* __restrict__ src, float* __restrict__ dst, int K) {
    int K4 = K >> 2;
    int i = blockIdx.x * blockDim.x + threadIdx.x;   // over NG*K4 float4
    if (i >= NG * K4) return;
    int k4 = i % K4;
    int np = i / K4;
    int h = np >> 2, g = np & 3;
    const float4* s = (const float4*)(src + (size_t)(g * HID + h) * K);
    ((float4*)(dst + (size_t)np * K))[k4] = s[k4];
}

// w_ih0 [4096, 42] -> interleaved, K-padded to 48 with zeros.
__global__ void permute_wih0(const float* __restrict__ src, float* __restrict__ dst) {
    int i = blockIdx.x * blockDim.x + threadIdx.x;   // over NG*KP
    if (i >= NG * KP) return;
    int k = i % KP;
    int np = i / KP;
    int h = np >> 2, g = np & 3;
    dst[i] = (k < VOC) ? src[(g * HID + h) * VOC + k] : 0.0f;
}

__global__ void prep_bias(const float* __restrict__ bih, const float* __restrict__ bhh,
                          float* __restrict__ dst) {
    int np = blockIdx.x * blockDim.x + threadIdx.x;
    if (np >= NG) return;
    int h = np >> 2, g = np & 3;
    dst[np] = bih[g * HID + h] + bhh[g * HID + h];
}

__global__ void init_states(float* __restrict__ h1, float* __restrict__ c0,
                            float* __restrict__ c1, float* __restrict__ x) {
    int i = blockIdx.x * blockDim.x + threadIdx.x;
    if (i < BATCH * HID) { h1[i] = 0.0f; c0[i] = 0.0f; c1[i] = 0.0f; }
    if (i < BATCH * KP)  { x[i] = ((i % KP) == (VOC - 1)) ? 1.0f : 0.0f; }
}

// fc1: h0[m][j] = sum_k latent[m][k]*w[j][k] + b[j], M=2048, J=1024, K=256 (runs once)
__global__ void fc1_kernel(const float* __restrict__ latent, const float* __restrict__ w,
                           const float* __restrict__ b, float* __restrict__ h0) {
    __shared__ float As[16][17];
    __shared__ float Ws[16][17];
    int tx = threadIdx.x, ty = threadIdx.y;
    int m = blockIdx.y * 16 + ty;
    int j = blockIdx.x * 16 + tx;
    float acc = 0.0f;
    for (int k0 = 0; k0 < 256; k0 += 16) {
        As[ty][tx] = latent[m * 256 + k0 + tx];
        Ws[ty][tx] = w[(blockIdx.x * 16 + ty) * 256 + k0 + tx];
        __syncthreads();
        #pragma unroll
        for (int kk = 0; kk < 16; kk++) acc += As[ty][kk] * Ws[tx][kk];
        __syncthreads();
    }
    h0[m * HID + j] = acc + b[j];
}

// ---------------- fused TF32 GEMM + LSTM cell ----------------
// gates[B, 4H] = A1@W1^T + A2@W2^T + bias   (W interleaved: col n' = 4h+g, gate order i,f,g,o)
// then per (b,h): c' = sig(f)*c + sig(i)*tanh(g); h' = sig(o)*tanh(c')
// Tile 128x128x16, 256 threads (8 warps, 4x2, warp tile 32x64), double-buffered cp.async.
#define GEMM_SMEM_BYTES 40960

__global__ void __launch_bounds__(256, 2) gemm_lstm(
    const float* __restrict__ A1, const float* __restrict__ W1, int K1,
    const float* __restrict__ A2, const float* __restrict__ W2, int K2,
    const float* __restrict__ bias, float* __restrict__ c_state,
    float* __restrict__ h_out) {
    extern __shared__ float sm[];
    float* As = sm;            // [2][128][20]
    float* Bs = sm + 5120;     // [2][128][20]

    const int tid  = threadIdx.x;
    const int bm   = blockIdx.y;     // M tile (batch)
    const int bn   = blockIdx.x;     // N tile (gate cols)
    const int lane = tid & 31, warp = tid >> 5;
    const int wm   = warp & 3, wn = warp >> 2;
    const int gid  = lane >> 2, qid = lane & 3;
    const int ldr  = tid >> 2;           // 0..63
    const int ldc  = (tid & 3) << 2;     // 0,4,8,12

    float acc[2][8][4];
    #pragma unroll
    for (int i = 0; i < 2; i++)
        #pragma unroll
        for (int j = 0; j < 8; j++)
            #pragma unroll
            for (int k = 0; k < 4; k++) acc[i][j][k] = 0.0f;

    int buf = 0;
    #pragma unroll 1
    for (int seg = 0; seg < 2; seg++) {
        const float* Aseg = seg ? A2 : A1;
        const float* Wseg = seg ? W2 : W1;
        const int K = seg ? K2 : K1;
        const float* Ab = Aseg + (size_t)bm * 128 * K;
        const float* Wb = Wseg + (size_t)bn * 128 * K;
        const int nk = K >> 4;

        {   // prologue: tile 0 -> buf
            float* Ad = As + buf * 2560;
            float* Bd = Bs + buf * 2560;
            cp16(Ad + ldr * 20 + ldc,        Ab + (size_t)ldr * K + ldc);
            cp16(Ad + (ldr + 64) * 20 + ldc, Ab + (size_t)(ldr + 64) * K + ldc);
            cp16(Bd + ldr * 20 + ldc,        Wb + (size_t)ldr * K + ldc);
            cp16(Bd + (ldr + 64) * 20 + ldc, Wb + (size_t)(ldr + 64) * K + ldc);
            asm volatile("cp.async.commit_group;" ::: "memory");
        }

        #pragma unroll 1
        for (int kt = 0; kt < nk; kt++) {
            if (kt + 1 < nk) {
                int k0 = (kt + 1) << 4;
                float* Ad = As + (buf ^ 1) * 2560;
                float* Bd = Bs + (buf ^ 1) * 2560;
                cp16(Ad + ldr * 20 + ldc,        Ab + (size_t)ldr * K + k0 + ldc);
                cp16(Ad + (ldr + 64) * 20 + ldc, Ab + (size_t)(ldr + 64) * K + k0 + ldc);
                cp16(Bd + ldr * 20 + ldc,        Wb + (size_t)ldr * K + k0 + ldc);
                cp16(Bd + (ldr + 64) * 20 + ldc, Wb + (size_t)(ldr + 64) * K + k0 + ldc);
                asm volatile("cp.async.commit_group;" ::: "memory");
                asm volatile("cp.async.wait_group 1;" ::: "memory");
            } else {
                asm volatile("cp.async.wait_group 0;" ::: "memory");
            }
            __syncthreads();

            const float* Ac = As + buf * 2560;
            const float* Bc = Bs + buf * 2560;
            #pragma unroll
            for (int k8 = 0; k8 < 16; k8 += 8) {
                unsigned a[2][4];
                #pragma unroll
                for (int mf = 0; mf < 2; mf++) {
                    int r = wm * 32 + mf * 16 + gid;
                    a[mf][0] = f2tf(Ac[r * 20 + k8 + qid]);
                    a[mf][1] = f2tf(Ac[(r + 8) * 20 + k8 + qid]);
                    a[mf][2] = f2tf(Ac[r * 20 + k8 + qid + 4]);
                    a[mf][3] = f2tf(Ac[(r + 8) * 20 + k8 + qid + 4]);
                }
                #pragma unroll
                for (int nf = 0; nf < 8; nf++) {
                    int n = wn * 64 + nf * 8 + gid;
                    unsigned b0 = f2tf(Bc[n * 20 + k8 + qid]);
                    unsigned b1 = f2tf(Bc[n * 20 + k8 + qid + 4]);
                    mma8(acc[0][nf], a[0][0], a[0][1], a[0][2], a[0][3], b0, b1);
                    mma8(acc[1][nf], a[1][0], a[1][1], a[1][2], a[1][3], b0, b1);
                }
            }
            __syncthreads();
            buf ^= 1;
        }
    }

    // -------- fused LSTM cell epilogue (smem reused) --------
    float* Cs    = sm;                 // [128][33]
    float* Hs    = sm + 128 * 33;      // [128][33]
    float* Bbias = sm + 2 * 128 * 33;  // [128]
    const int jbase = bn * 32;         // hidden-unit base of this tile

    for (int e = tid; e < 128 * 32; e += 256) {
        int r = e >> 5, j = e & 31;
        Cs[r * 33 + j] = c_state[(size_t)(bm * 128 + r) * HID + jbase + j];
    }
    if (tid < 128) Bbias[tid] = bias[bn * 128 + tid];
    __syncthreads();

    #pragma unroll
    for (int mf = 0; mf < 2; mf++) {
        #pragma unroll
        for (int nf = 0; nf < 8; nf++) {
            int r  = wm * 32 + mf * 16 + gid;
            int cb = wn * 64 + nf * 8 + 2 * qid;
            float bv0 = Bbias[cb], bv1 = Bbias[cb + 1];
            float v0 = acc[mf][nf][0] + bv0;
            float v1 = acc[mf][nf][1] + bv1;
            float v2 = acc[mf][nf][2] + bv0;
            float v3 = acc[mf][nf][3] + bv1;
            // pair (i,f) lane with (g,o) lane
            float p0 = __shfl_xor_sync(0xffffffffu, v0, 1);
            float p1 = __shfl_xor_sync(0xffffffffu, v1, 1);
            float p2 = __shfl_xor_sync(0xffffffffu, v2, 1);
            float p3 = __shfl_xor_sync(0xffffffffu, v3, 1);
            if (!(qid & 1)) {
                int jl = wn * 16 + nf * 2 + (qid >> 1);
                {
                    float co = Cs[r * 33 + jl];
                    float cn = sigmoidf(v1) * co + sigmoidf(v0) * tanhf(p0);
                    float hn = sigmoidf(p1) * tanhf(cn);
                    Cs[r * 33 + jl] = cn;
                    Hs[r * 33 + jl] = hn;
                }
                {
                    float co = Cs[(r + 8) * 33 + jl];
                    float cn = sigmoidf(v3) * co + sigmoidf(v2) * tanhf(p2);
                    float hn = sigmoidf(p3) * tanhf(cn);
                    Cs[(r + 8) * 33 + jl] = cn;
                    Hs[(r + 8) * 33 + jl] = hn;
                }
            }
        }
    }
    __syncthreads();

    for (int e = tid; e < 128 * 32; e += 256) {
        int r = e >> 5, j = e & 31;
        size_t gix = (size_t)(bm * 128 + r) * HID + jbase + j;
        c_state[gix] = Cs[r * 33 + j];
        h_out[gix]   = Hs[r * 33 + j];
    }
}

// ---------------- logits + softmax feedback ----------------
// 128 blocks x 256 threads; fc2_w (42x1024) staged in smem; warp handles 2 rows.
#define LOGITS_SMEM_BYTES ((VOC * HID + 16 * KP) * 4)

__global__ void __launch_bounds__(256) logits_kernel(
    const float* __restrict__ h, const float* __restrict__ fc2_w,
    const float* __restrict__ fc2_b, float* __restrict__ out,
    float* __restrict__ x, int t) {
    extern __shared__ float sw[];                 // [42*1024] weights
    float* ls = sw + VOC * HID;                   // [16][48] logits stage
    const int tid = threadIdx.x;
    const int warp = tid >> 5, lane = tid & 31;

    float4* sw4 = (float4*)sw;
    const float4* gw4 = (const float4*)fc2_w;
    for (int i = tid; i < VOC * (HID / 4); i += 256) sw4[i] = gw4[i];
    __syncthreads();

    const int r0 = blockIdx.x * 16 + warp * 2;    // this warp: rows r0, r0+1
    const float4* h4 = (const float4*)h;
    float4 ha[8], hb[8];
    #pragma unroll
    for (int i = 0; i < 8; i++) {
        ha[i] = h4[(size_t)r0 * 256 + i * 32 + lane];
        hb[i] = h4[(size_t)(r0 + 1) * 256 + i * 32 + lane];
    }

    for (int v = 0; v < VOC; v++) {
        float sa = 0.0f, sb = 0.0f;
        #pragma unroll
        for (int i = 0; i < 8; i++) {
            float4 w4 = sw4[v * 256 + i * 32 + lane];
            sa += ha[i].x * w4.x + ha[i].y * w4.y + ha[i].z * w4.z + ha[i].w * w4.w;
            sb += hb[i].x * w4.x + hb[i].y * w4.y + hb[i].z * w4.z + hb[i].w * w4.w;
        }
        #pragma unroll
        for (int o = 16; o; o >>= 1) {
            sa += __shfl_xor_sync(0xffffffffu, sa, o);
            sb += __shfl_xor_sync(0xffffffffu, sb, o);
        }
        if (lane == 0) {
            float bv = fc2_b[v];
            float la = sa + bv, lb = sb + bv;
            ls[(warp * 2) * KP + v]     = la;
            ls[(warp * 2 + 1) * KP + v] = lb;
            out[((size_t)r0 * SEQ + t) * VOC + v]       = la;   // pre-softmax logits
            out[((size_t)(r0 + 1) * SEQ + t) * VOC + v] = lb;
        }
    }
    __syncwarp();

    #pragma unroll
    for (int rr = 0; rr < 2; rr++) {
        int r = r0 + rr;
        float v1 = (lane < VOC)      ? ls[(warp * 2 + rr) * KP + lane]      : -1e30f;
        float v2 = (lane + 32 < VOC) ? ls[(warp * 2 + rr) * KP + lane + 32] : -1e30f;
        float m = fmaxf(v1, v2);
        #pragma unroll
        for (int o = 16; o; o >>= 1) m = fmaxf(m, __shfl_xor_sync(0xffffffffu, m, o));
        float e1 = (lane < VOC)      ? expf(v1 - m) : 0.0f;
        float e2 = (lane + 32 < VOC) ? expf(v2 - m) : 0.0f;
        float s = e1 + e2;
        #pragma unroll
        for (int o = 16; o; o >>= 1) s += __shfl_xor_sync(0xffffffffu, s, o);
        float inv = 1.0f / s;
        if (lane < VOC)      x[(size_t)r * KP + lane]      = e1 * inv;
        if (lane + 32 < VOC) x[(size_t)r * KP + lane + 32] = e2 * inv;
    }
}

// ---------------- host ----------------
extern "C" void kernel_launch(void* const* d_in, const int* in_sizes, int n_in,
                              void* d_out, int out_size) {
    const float* latent = (const float*)d_in[0];
    const float* fc1_w  = (const float*)d_in[1];
    const float* fc1_b  = (const float*)d_in[2];
    const float* fc2_w  = (const float*)d_in[3];
    const float* fc2_b  = (const float*)d_in[4];
    const float* w_ih0  = (const float*)d_in[5];
    const float* w_hh0  = (const float*)d_in[6];
    const float* b_ih0  = (const float*)d_in[7];
    const float* b_hh0  = (const float*)d_in[8];
    const float* w_ih1  = (const float*)d_in[9];
    const float* w_hh1  = (const float*)d_in[10];
    const float* b_ih1  = (const float*)d_in[11];
    const float* b_hh1  = (const float*)d_in[12];
    float* out = (float*)d_out;

    float *Whh0, *Wih1, *Whh1, *Wih0, *b0, *b1;
    float *h0a, *h0b, *h1a, *h1b, *c0, *c1, *x;
    cudaGetSymbolAddress((void**)&Whh0, g_Whh0);
    cudaGetSymbolAddress((void**)&Wih1, g_Wih1);
    cudaGetSymbolAddress((void**)&Whh1, g_Whh1);
    cudaGetSymbolAddress((void**)&Wih0, g_Wih0);
    cudaGetSymbolAddress((void**)&b0, g_b0);
    cudaGetSymbolAddress((void**)&b1, g_b1);
    cudaGetSymbolAddress((void**)&h0a, g_h0a);
    cudaGetSymbolAddress((void**)&h0b, g_h0b);
    cudaGetSymbolAddress((void**)&h1a, g_h1a);
    cudaGetSymbolAddress((void**)&h1b, g_h1b);
    cudaGetSymbolAddress((void**)&c0, g_c0);
    cudaGetSymbolAddress((void**)&c1, g_c1);
    cudaGetSymbolAddress((void**)&x, g_x);

    cudaFuncSetAttribute(logits_kernel, cudaFuncAttributeMaxDynamicSharedMemorySize,
                         LOGITS_SMEM_BYTES);
    cudaFuncSetAttribute(gemm_lstm, cudaFuncAttributeMaxDynamicSharedMemorySize,
                         GEMM_SMEM_BYTES);

    // prep: interleave gate weights, combine biases, init states/x0, fc1
    {
        int n = NG * (HID / 4);
        permute_w<<<(n + 255) / 256, 256>>>(w_hh0, Whh0, HID);
        permute_w<<<(n + 255) / 256, 256>>>(w_ih1, Wih1, HID);
        permute_w<<<(n + 255) / 256, 256>>>(w_hh1, Whh1, HID);
    }
    permute_wih0<<<(NG * KP + 255) / 256, 256>>>(w_ih0, Wih0);
    prep_bias<<<(NG + 255) / 256, 256>>>(b_ih0, b_hh0, b0);
    prep_bias<<<(NG + 255) / 256, 256>>>(b_ih1, b_hh1, b1);
    init_states<<<(BATCH * HID + 255) / 256, 256>>>(h1a, c0, c1, x);
    fc1_kernel<<<dim3(HID / 16, BATCH / 16), dim3(16, 16)>>>(latent, fc1_w, fc1_b, h0a);

    float* h0bufs[2] = {h0a, h0b};
    float* h1bufs[2] = {h1a, h1b};
    dim3 ggrid(NG / 128, BATCH / 128);  // (32, 16)

    for (int t = 0; t < SEQ; t++) {
        float* h0i = h0bufs[t & 1];
        float* h0o = h0bufs[(t + 1) & 1];
        float* h1i = h1bufs[t & 1];
        float* h1o = h1bufs[(t + 1) & 1];
        // layer 0: gates = x@Wih0' + h0@Whh0' + b0 ; fused cell -> h0o, c0
        gemm_lstm<<<ggrid, 256, GEMM_SMEM_BYTES>>>(x, Wih0, KP, h0i, Whh0, HID,
                                                   b0, c0, h0o);
        // layer 1: gates = h0o@Wih1' + h1@Whh1' + b1 ; fused cell -> h1o, c1
        gemm_lstm<<<ggrid, 256, GEMM_SMEM_BYTES>>>(h0o, Wih1, HID, h1i, Whh1, HID,
                                                   b1, c1, h1o);
        // logits (written to out) + softmax feedback into x
        logits_kernel<<<BATCH / 16, 256, LOGITS_SMEM_BYTES>>>(h1o, fc2_w, fc2_b,
                                                              out, x, t);
    }
}

// round 11
// speedup vs baseline: 1.0101x; 1.0101x over previous
#include <cuda_runtime.h>
#include <cstdint>
#include <cstddef>
#include <math.h>

#define SEQ   100
#define BATCH 2048
#define HID   1024
#define VOC   42
#define NG    4096   // 4*HID
#define KP    48     // padded K for x / w_ih0 (42 -> 48, multiple of 16)

// ---------------- scratch (device globals; no allocation allowed) ----------------
__device__ __align__(256) float g_Whh0[NG * HID];
__device__ __align__(256) float g_Wih1[NG * HID];
__device__ __align__(256) float g_Whh1[NG * HID];
__device__ __align__(256) float g_Wih0[NG * KP];
__device__ __align__(256) float g_b0[NG];
__device__ __align__(256) float g_b1[NG];
__device__ __align__(256) float g_h0a[BATCH * HID];
__device__ __align__(256) float g_h0b[BATCH * HID];
__device__ __align__(256) float g_h1a[BATCH * HID];
__device__ __align__(256) float g_h1b[BATCH * HID];
__device__ __align__(256) float g_c0[BATCH * HID];
__device__ __align__(256) float g_c1[BATCH * HID];
__device__ __align__(256) float g_x[BATCH * KP];

// ---------------- small helpers ----------------
__device__ __forceinline__ unsigned f2tf(float f) {
    unsigned u;
    asm("cvt.rna.tf32.f32 %0, %1;" : "=r"(u) : "f"(f));
    return u;
}
__device__ __forceinline__ float tf32r(float f) { return __uint_as_float(f2tf(f)); }

// operands are pre-rounded to tf32 at their producers; pass raw bits
__device__ __forceinline__ void mma8(float c[4],
                                     float a0, float a1, float a2, float a3,
                                     float b0, float b1) {
    asm volatile(
        "mma.sync.aligned.m16n8k8.row.col.f32.tf32.tf32.f32 "
        "{%0,%1,%2,%3}, {%4,%5,%6,%7}, {%8,%9}, {%0,%1,%2,%3};"
        : "+f"(c[0]), "+f"(c[1]), "+f"(c[2]), "+f"(c[3])
        : "r"(__float_as_uint(a0)), "r"(__float_as_uint(a1)),
          "r"(__float_as_uint(a2)), "r"(__float_as_uint(a3)),
          "r"(__float_as_uint(b0)), "r"(__float_as_uint(b1)));
}

__device__ __forceinline__ void cp16(float* dst, const float* src) {
    unsigned s = (unsigned)__cvta_generic_to_shared(dst);
    asm volatile("cp.async.cg.shared.global [%0], [%1], 16;\n" :: "r"(s), "l"(src) : "memory");
}

__device__ __forceinline__ float sigmoidf(float x) { return 1.0f / (1.0f + expf(-x)); }

// ---------------- prep kernels ----------------
// Interleave gate rows: dst[(4h+g)*K + k] = tf32(src[(g*HID + h)*K + k]).
__global__ void permute_w(const float* __restrict__ src, float* __restrict__ dst, int K) {
    int K4 = K >> 2;
    int i = blockIdx.x * blockDim.x + threadIdx.x;   // over NG*K4 float4
    if (i >= NG * K4) return;
    int k4 = i % K4;
    int np = i / K4;
    int h = np >> 2, g = np & 3;
    float4 v = ((const float4*)(src + (size_t)(g * HID + h) * K))[k4];
    v.x = tf32r(v.x); v.y = tf32r(v.y); v.z = tf32r(v.z); v.w = tf32r(v.w);
    ((float4*)(dst + (size_t)np * K))[k4] = v;
}

// w_ih0 [4096, 42] -> interleaved, K-padded to 48 with zeros, tf32-rounded.
__global__ void permute_wih0(const float* __restrict__ src, float* __restrict__ dst) {
    int i = blockIdx.x * blockDim.x + threadIdx.x;   // over NG*KP
    if (i >= NG * KP) return;
    int k = i % KP;
    int np = i / KP;
    int h = np >> 2, g = np & 3;
    dst[i] = (k < VOC) ? tf32r(src[(g * HID + h) * VOC + k]) : 0.0f;
}

__global__ void prep_bias(const float* __restrict__ bih, const float* __restrict__ bhh,
                          float* __restrict__ dst) {
    int np = blockIdx.x * blockDim.x + threadIdx.x;
    if (np >= NG) return;
    int h = np >> 2, g = np & 3;
    dst[np] = bih[g * HID + h] + bhh[g * HID + h];
}

__global__ void init_states(float* __restrict__ h1, float* __restrict__ c0,
                            float* __restrict__ c1, float* __restrict__ x) {
    int i = blockIdx.x * blockDim.x + threadIdx.x;
    if (i < BATCH * HID) { h1[i] = 0.0f; c0[i] = 0.0f; c1[i] = 0.0f; }
    if (i < BATCH * KP)  { x[i] = ((i % KP) == (VOC - 1)) ? 1.0f : 0.0f; }
}

// fc1: h0[m][j] = tf32(sum_k latent[m][k]*w[j][k] + b[j])
__global__ void fc1_kernel(const float* __restrict__ latent, const float* __restrict__ w,
                           const float* __restrict__ b, float* __restrict__ h0) {
    __shared__ float As[16][17];
    __shared__ float Ws[16][17];
    int tx = threadIdx.x, ty = threadIdx.y;
    int m = blockIdx.y * 16 + ty;
    int j = blockIdx.x * 16 + tx;
    float acc = 0.0f;
    for (int k0 = 0; k0 < 256; k0 += 16) {
        As[ty][tx] = latent[m * 256 + k0 + tx];
        Ws[ty][tx] = w[(blockIdx.x * 16 + ty) * 256 + k0 + tx];
        __syncthreads();
        #pragma unroll
        for (int kk = 0; kk < 16; kk++) acc += As[ty][kk] * Ws[tx][kk];
        __syncthreads();
    }
    h0[m * HID + j] = tf32r(acc + b[j]);
}

// ---------------- fused TF32 GEMM + LSTM cell ----------------
// gates[B, 4H] = A1@W1^T + A2@W2^T + bias   (W interleaved: col n' = 4h+g, gate order i,f,g,o)
// then per (b,h): c' = sig(f)*c + sig(i)*tanh(g); h' = sig(o)*tanh(c')
// Tile 128x128x16, 256 threads (8 warps, 4x2, warp tile 32x64), double-buffered cp.async.
#define GEMM_SMEM_BYTES 40960

__global__ void __launch_bounds__(256, 2) gemm_lstm(
    const float* __restrict__ A1, const float* __restrict__ W1, int K1,
    const float* __restrict__ A2, const float* __restrict__ W2, int K2,
    const float* __restrict__ bias, float* __restrict__ c_state,
    float* __restrict__ h_out) {
    extern __shared__ float sm[];
    float* As = sm;            // [2][128][20]
    float* Bs = sm + 5120;     // [2][128][20]

    const int tid  = threadIdx.x;
    const int bm   = blockIdx.y;     // M tile (batch)
    const int bn   = blockIdx.x;     // N tile (gate cols)
    const int lane = tid & 31, warp = tid >> 5;
    const int wm   = warp & 3, wn = warp >> 2;
    const int gid  = lane >> 2, qid = lane & 3;
    const int ldr  = tid >> 2;           // 0..63
    const int ldc  = (tid & 3) << 2;     // 0,4,8,12

    float acc[2][8][4];
    #pragma unroll
    for (int i = 0; i < 2; i++)
        #pragma unroll
        for (int j = 0; j < 8; j++)
            #pragma unroll
            for (int k = 0; k < 4; k++) acc[i][j][k] = 0.0f;

    int buf = 0;
    #pragma unroll 1
    for (int seg = 0; seg < 2; seg++) {
        const float* Aseg = seg ? A2 : A1;
        const float* Wseg = seg ? W2 : W1;
        const int K = seg ? K2 : K1;
        const float* Ab = Aseg + (size_t)bm * 128 * K;
        const float* Wb = Wseg + (size_t)bn * 128 * K;
        const int nk = K >> 4;

        {   // prologue: tile 0 -> buf
            float* Ad = As + buf * 2560;
            float* Bd = Bs + buf * 2560;
            cp16(Ad + ldr * 20 + ldc,        Ab + (size_t)ldr * K + ldc);
            cp16(Ad + (ldr + 64) * 20 + ldc, Ab + (size_t)(ldr + 64) * K + ldc);
            cp16(Bd + ldr * 20 + ldc,        Wb + (size_t)ldr * K + ldc);
            cp16(Bd + (ldr + 64) * 20 + ldc, Wb + (size_t)(ldr + 64) * K + ldc);
            asm volatile("cp.async.commit_group;" ::: "memory");
        }

        #pragma unroll 1
        for (int kt = 0; kt < nk; kt++) {
            if (kt + 1 < nk) {
                int k0 = (kt + 1) << 4;
                float* Ad = As + (buf ^ 1) * 2560;
                float* Bd = Bs + (buf ^ 1) * 2560;
                cp16(Ad + ldr * 20 + ldc,        Ab + (size_t)ldr * K + k0 + ldc);
                cp16(Ad + (ldr + 64) * 20 + ldc, Ab + (size_t)(ldr + 64) * K + k0 + ldc);
                cp16(Bd + ldr * 20 + ldc,        Wb + (size_t)ldr * K + k0 + ldc);
                cp16(Bd + (ldr + 64) * 20 + ldc, Wb + (size_t)(ldr + 64) * K + k0 + ldc);
                asm volatile("cp.async.commit_group;" ::: "memory");
                asm volatile("cp.async.wait_group 1;" ::: "memory");
            } else {
                asm volatile("cp.async.wait_group 0;" ::: "memory");
            }
            __syncthreads();

            const float* Ac = As + buf * 2560;
            const float* Bc = Bs + buf * 2560;
            #pragma unroll
            for (int k8 = 0; k8 < 16; k8 += 8) {
                // hoist all fragment loads for this k8 step (operands pre-rounded)
                float a[2][4];
                #pragma unroll
                for (int mf = 0; mf < 2; mf++) {
                    int r = wm * 32 + mf * 16 + gid;
                    a[mf][0] = Ac[r * 20 + k8 + qid];
                    a[mf][1] = Ac[(r + 8) * 20 + k8 + qid];
                    a[mf][2] = Ac[r * 20 + k8 + qid + 4];
                    a[mf][3] = Ac[(r + 8) * 20 + k8 + qid + 4];
                }
                float b[8][2];
                #pragma unroll
                for (int nf = 0; nf < 8; nf++) {
                    int n = wn * 64 + nf * 8 + gid;
                    b[nf][0] = Bc[n * 20 + k8 + qid];
                    b[nf][1] = Bc[n * 20 + k8 + qid + 4];
                }
                #pragma unroll
                for (int nf = 0; nf < 8; nf++) {
                    mma8(acc[0][nf], a[0][0], a[0][1], a[0][2], a[0][3],
                         b[nf][0], b[nf][1]);
                    mma8(acc[1][nf], a[1][0], a[1][1], a[1][2], a[1][3],
                         b[nf][0], b[nf][1]);
                }
            }
            __syncthreads();
            buf ^= 1;
        }
    }

    // -------- fused LSTM cell epilogue (smem reused) --------
    float* Cs    = sm;                 // [128][33]
    float* Hs    = sm + 128 * 33;      // [128][33]
    float* Bbias = sm + 2 * 128 * 33;  // [128]
    const int jbase = bn * 32;         // hidden-unit base of this tile

    for (int e = tid; e < 128 * 32; e += 256) {
        int r = e >> 5, j = e & 31;
        Cs[r * 33 + j] = c_state[(size_t)(bm * 128 + r) * HID + jbase + j];
    }
    if (tid < 128) Bbias[tid] = bias[bn * 128 + tid];
    __syncthreads();

    #pragma unroll
    for (int mf = 0; mf < 2; mf++) {
        #pragma unroll
        for (int nf = 0; nf < 8; nf++) {
            int r  = wm * 32 + mf * 16 + gid;
            int cb = wn * 64 + nf * 8 + 2 * qid;
            float bv0 = Bbias[cb], bv1 = Bbias[cb + 1];
            float v0 = acc[mf][nf][0] + bv0;
            float v1 = acc[mf][nf][1] + bv1;
            float v2 = acc[mf][nf][2] + bv0;
            float v3 = acc[mf][nf][3] + bv1;
            // pair (i,f) lane with (g,o) lane
            float p0 = __shfl_xor_sync(0xffffffffu, v0, 1);
            float p1 = __shfl_xor_sync(0xffffffffu, v1, 1);
            float p2 = __shfl_xor_sync(0xffffffffu, v2, 1);
            float p3 = __shfl_xor_sync(0xffffffffu, v3, 1);
            if (!(qid & 1)) {
                int jl = wn * 16 + nf * 2 + (qid >> 1);
                {
                    float co = Cs[r * 33 + jl];
                    float cn = sigmoidf(v1) * co + sigmoidf(v0) * tanhf(p0);
                    float hn = sigmoidf(p1) * tanhf(cn);
                    Cs[r * 33 + jl] = cn;
                    Hs[r * 33 + jl] = tf32r(hn);   // pre-round: h is the next GEMM's A
                }
                {
                    float co = Cs[(r + 8) * 33 + jl];
                    float cn = sigmoidf(v3) * co + sigmoidf(v2) * tanhf(p2);
                    float hn = sigmoidf(p3) * tanhf(cn);
                    Cs[(r + 8) * 33 + jl] = cn;
                    Hs[(r + 8) * 33 + jl] = tf32r(hn);
                }
            }
        }
    }
    __syncthreads();

    for (int e = tid; e < 128 * 32; e += 256) {
        int r = e >> 5, j = e & 31;
        size_t gix = (size_t)(bm * 128 + r) * HID + jbase + j;
        c_state[gix] = Cs[r * 33 + j];
        h_out[gix]   = Hs[r * 33 + j];
    }
}

// ---------------- logits + softmax feedback ----------------
// 128 blocks x 256 threads; fc2_w (42x1024) staged in smem; warp handles 2 rows.
#define LOGITS_SMEM_BYTES ((VOC * HID + 16 * KP) * 4)

__global__ void __launch_bounds__(256) logits_kernel(
    const float* __restrict__ h, const float* __restrict__ fc2_w,
    const float* __restrict__ fc2_b, float* __restrict__ out,
    float* __restrict__ x, int t) {
    extern __shared__ float sw[];                 // [42*1024] weights
    float* ls = sw + VOC * HID;                   // [16][48] logits stage
    const int tid = threadIdx.x;
    const int warp = tid >> 5, lane = tid & 31;

    float4* sw4 = (float4*)sw;
    const float4* gw4 = (const float4*)fc2_w;
    for (int i = tid; i < VOC * (HID / 4); i += 256) sw4[i] = gw4[i];
    __syncthreads();

    const int r0 = blockIdx.x * 16 + warp * 2;    // this warp: rows r0, r0+1
    const float4* h4 = (const float4*)h;
    float4 ha[8], hb[8];
    #pragma unroll
    for (int i = 0; i < 8; i++) {
        ha[i] = h4[(size_t)r0 * 256 + i * 32 + lane];
        hb[i] = h4[(size_t)(r0 + 1) * 256 + i * 32 + lane];
    }

    for (int v = 0; v < VOC; v++) {
        float sa = 0.0f, sb = 0.0f;
        #pragma unroll
        for (int i = 0; i < 8; i++) {
            float4 w4 = sw4[v * 256 + i * 32 + lane];
            sa += ha[i].x * w4.x + ha[i].y * w4.y + ha[i].z * w4.z + ha[i].w * w4.w;
            sb += hb[i].x * w4.x + hb[i].y * w4.y + hb[i].z * w4.z + hb[i].w * w4.w;
        }
        #pragma unroll
        for (int o = 16; o; o >>= 1) {
            sa += __shfl_xor_sync(0xffffffffu, sa, o);
            sb += __shfl_xor_sync(0xffffffffu, sb, o);
        }
        if (lane == 0) {
            float bv = fc2_b[v];
            float la = sa + bv, lb = sb + bv;
            ls[(warp * 2) * KP + v]     = la;
            ls[(warp * 2 + 1) * KP + v] = lb;
            out[((size_t)r0 * SEQ + t) * VOC + v]       = la;   // pre-softmax logits
            out[((size_t)(r0 + 1) * SEQ + t) * VOC + v] = lb;
        }
    }
    __syncwarp();

    #pragma unroll
    for (int rr = 0; rr < 2; rr++) {
        int r = r0 + rr;
        float v1 = (lane < VOC)      ? ls[(warp * 2 + rr) * KP + lane]      : -1e30f;
        float v2 = (lane + 32 < VOC) ? ls[(warp * 2 + rr) * KP + lane + 32] : -1e30f;
        float m = fmaxf(v1, v2);
        #pragma unroll
        for (int o = 16; o; o >>= 1) m = fmaxf(m, __shfl_xor_sync(0xffffffffu, m, o));
        float e1 = (lane < VOC)      ? expf(v1 - m) : 0.0f;
        float e2 = (lane + 32 < VOC) ? expf(v2 - m) : 0.0f;
        float s = e1 + e2;
        #pragma unroll
        for (int o = 16; o; o >>= 1) s += __shfl_xor_sync(0xffffffffu, s, o);
        float inv = 1.0f / s;
        if (lane < VOC)      x[(size_t)r * KP + lane]      = tf32r(e1 * inv);
        if (lane + 32 < VOC) x[(size_t)r * KP + lane + 32] = tf32r(e2 * inv);
    }
}

// ---------------- host ----------------
extern "C" void kernel_launch(void* const* d_in, const int* in_sizes, int n_in,
                              void* d_out, int out_size) {
    const float* latent = (const float*)d_in[0];
    const float* fc1_w  = (const float*)d_in[1];
    const float* fc1_b  = (const float*)d_in[2];
    const float* fc2_w  = (const float*)d_in[3];
    const float* fc2_b  = (const float*)d_in[4];
    const float* w_ih0  = (const float*)d_in[5];
    const float* w_hh0  = (const float*)d_in[6];
    const float* b_ih0  = (const float*)d_in[7];
    const float* b_hh0  = (const float*)d_in[8];
    const float* w_ih1  = (const float*)d_in[9];
    const float* w_hh1  = (const float*)d_in[10];
    const float* b_ih1  = (const float*)d_in[11];
    const float* b_hh1  = (const float*)d_in[12];
    float* out = (float*)d_out;

    float *Whh0, *Wih1, *Whh1, *Wih0, *b0, *b1;
    float *h0a, *h0b, *h1a, *h1b, *c0, *c1, *x;
    cudaGetSymbolAddress((void**)&Whh0, g_Whh0);
    cudaGetSymbolAddress((void**)&Wih1, g_Wih1);
    cudaGetSymbolAddress((void**)&Whh1, g_Whh1);
    cudaGetSymbolAddress((void**)&Wih0, g_Wih0);
    cudaGetSymbolAddress((void**)&b0, g_b0);
    cudaGetSymbolAddress((void**)&b1, g_b1);
    cudaGetSymbolAddress((void**)&h0a, g_h0a);
    cudaGetSymbolAddress((void**)&h0b, g_h0b);
    cudaGetSymbolAddress((void**)&h1a, g_h1a);
    cudaGetSymbolAddress((void**)&h1b, g_h1b);
    cudaGetSymbolAddress((void**)&c0, g_c0);
    cudaGetSymbolAddress((void**)&c1, g_c1);
    cudaGetSymbolAddress((void**)&x, g_x);

    cudaFuncSetAttribute(logits_kernel, cudaFuncAttributeMaxDynamicSharedMemorySize,
                         LOGITS_SMEM_BYTES);
    cudaFuncSetAttribute(gemm_lstm, cudaFuncAttributeMaxDynamicSharedMemorySize,
                         GEMM_SMEM_BYTES);

    // prep: interleave gate weights (tf32-rounded), combine biases, init states/x0, fc1
    {
        int n = NG * (HID / 4);
        permute_w<<<(n + 255) / 256, 256>>>(w_hh0, Whh0, HID);
        permute_w<<<(n + 255) / 256, 256>>>(w_ih1, Wih1, HID);
        permute_w<<<(n + 255) / 256, 256>>>(w_hh1, Whh1, HID);
    }
    permute_wih0<<<(NG * KP + 255) / 256, 256>>>(w_ih0, Wih0);
    prep_bias<<<(NG + 255) / 256, 256>>>(b_ih0, b_hh0, b0);
    prep_bias<<<(NG + 255) / 256, 256>>>(b_ih1, b_hh1, b1);
    init_states<<<(BATCH * HID + 255) / 256, 256>>>(h1a, c0, c1, x);
    fc1_kernel<<<dim3(HID / 16, BATCH / 16), dim3(16, 16)>>>(latent, fc1_w, fc1_b, h0a);

    float* h0bufs[2] = {h0a, h0b};
    float* h1bufs[2] = {h1a, h1b};
    dim3 ggrid(NG / 128, BATCH / 128);  // (32, 16)

    for (int t = 0; t < SEQ; t++) {
        float* h0i = h0bufs[t & 1];
        float* h0o = h0bufs[(t + 1) & 1];
        float* h1i = h1bufs[t & 1];
        float* h1o = h1bufs[(t + 1) & 1];
        // layer 0: gates = x@Wih0' + h0@Whh0' + b0 ; fused cell -> h0o, c0
        gemm_lstm<<<ggrid, 256, GEMM_SMEM_BYTES>>>(x, Wih0, KP, h0i, Whh0, HID,
                                                   b0, c0, h0o);
        // layer 1: gates = h0o@Wih1' + h1@Whh1' + b1 ; fused cell -> h1o, c1
        gemm_lstm<<<ggrid, 256, GEMM_SMEM_BYTES>>>(h0o, Wih1, HID, h1i, Whh1, HID,
                                                   b1, c1, h1o);
        // logits (written to out) + softmax feedback into x
        logits_kernel<<<BATCH / 16, 256, LOGITS_SMEM_BYTES>>>(h1o, fc2_w, fc2_b,
                                                              out, x, t);
    }
}

// round 13
// speedup vs baseline: 1.7812x; 1.7634x over previous
#include <cuda_runtime.h>
#include <cuda_fp16.h>
#include <cstdint>
#include <cstddef>
#include <math.h>

#define SEQ   100
#define BATCH 2048
#define HID   1024
#define VOC   42
#define NG    4096   // 4*HID
#define KP    64     // padded K for x / w_ih0 (42 -> 64, multiple of 32)

// ---------------- scratch (device globals; no allocation allowed) ----------------
__device__ __align__(256) __half g_Whh0[NG * HID];
__device__ __align__(256) __half g_Wih1[NG * HID];
__device__ __align__(256) __half g_Whh1[NG * HID];
__device__ __align__(256) __half g_Wih0[NG * KP];
__device__ __align__(256) float  g_b0[NG];
__device__ __align__(256) float  g_b1[NG];
__device__ __align__(256) __half g_h0a[BATCH * HID];
__device__ __align__(256) __half g_h0b[BATCH * HID];
__device__ __align__(256) __half g_h1a[BATCH * HID];
__device__ __align__(256) __half g_h1b[BATCH * HID];
__device__ __align__(256) float  g_c0[BATCH * HID];
__device__ __align__(256) float  g_c1[BATCH * HID];
__device__ __align__(256) __half g_x[BATCH * KP];

// ---------------- small helpers ----------------
__device__ __forceinline__ void cp16(void* dst_smem, const void* src) {
    unsigned s = (unsigned)__cvta_generic_to_shared(dst_smem);
    asm volatile("cp.async.cg.shared.global [%0], [%1], 16;\n" :: "r"(s), "l"(src) : "memory");
}

// m16n8k16 fp16 MMA, fp32 accumulate. a: 4 b32 (8 halfs), b: 2 b32 (4 halfs).
__device__ __forceinline__ void mma16(float c[4],
                                      uint32_t a0, uint32_t a1, uint32_t a2, uint32_t a3,
                                      uint32_t b0, uint32_t b1) {
    asm volatile(
        "mma.sync.aligned.m16n8k16.row.col.f32.f16.f16.f32 "
        "{%0,%1,%2,%3}, {%4,%5,%6,%7}, {%8,%9}, {%0,%1,%2,%3};"
        : "+f"(c[0]), "+f"(c[1]), "+f"(c[2]), "+f"(c[3])
        : "r"(a0), "r"(a1), "r"(a2), "r"(a3), "r"(b0), "r"(b1));
}

__device__ __forceinline__ float sigmoidf(float x) { return 1.0f / (1.0f + expf(-x)); }

// ---------------- prep kernels (exactly 5 launches before first GEMM) ----------------
// (1) Interleave gate rows for the three [4H,HID] weights: dst[(4h+g)*K+k] = fp16(src[...])
__global__ void pack_w3(const float* __restrict__ s0, const float* __restrict__ s1,
                        const float* __restrict__ s2, __half* __restrict__ d0,
                        __half* __restrict__ d1, __half* __restrict__ d2) {
    const float* src = (blockIdx.y == 0) ? s0 : (blockIdx.y == 1) ? s1 : s2;
    __half* dst      = (blockIdx.y == 0) ? d0 : (blockIdx.y == 1) ? d1 : d2;
    int i = blockIdx.x * blockDim.x + threadIdx.x;   // over NG*HID
    if (i >= NG * HID) return;
    int k = i & (HID - 1);
    int np = i >> 10;
    int h = np >> 2, g = np & 3;
    dst[i] = __float2half_rn(src[(size_t)(g * HID + h) * HID + k]);
}

// (2) w_ih0 [4H,42] -> interleaved, K-padded to 64 with zeros.
__global__ void pack_wih0(const float* __restrict__ src, __half* __restrict__ dst) {
    int i = blockIdx.x * blockDim.x + threadIdx.x;   // over NG*KP
    if (i >= NG * KP) return;
    int k = i % KP;
    int np = i / KP;
    int h = np >> 2, g = np & 3;
    dst[i] = __float2half_rn((k < VOC) ? src[(g * HID + h) * VOC + k] : 0.0f);
}

// (3) both combined biases
__global__ void prep_bias2(const float* __restrict__ bih0, const float* __restrict__ bhh0,
                           const float* __restrict__ bih1, const float* __restrict__ bhh1,
                           float* __restrict__ d0, float* __restrict__ d1) {
    int np = blockIdx.x * blockDim.x + threadIdx.x;
    if (np >= NG) return;
    int h = np >> 2, g = np & 3;
    d0[np] = bih0[g * HID + h] + bhh0[g * HID + h];
    d1[np] = bih1[g * HID + h] + bhh1[g * HID + h];
}

// (4) zero states, one-hot x
__global__ void init_states(__half* __restrict__ h1, float* __restrict__ c0,
                            float* __restrict__ c1, __half* __restrict__ x) {
    int i = blockIdx.x * blockDim.x + threadIdx.x;
    if (i < BATCH * HID) { h1[i] = __float2half_rn(0.0f); c0[i] = 0.0f; c1[i] = 0.0f; }
    if (i < BATCH * KP)  x[i] = __float2half_rn(((i % KP) == (VOC - 1)) ? 1.0f : 0.0f);
}

// (5) fc1: h0[m][j] = fp16(latent[m]·fc1_w[j] + b[j])
__global__ void fc1_kernel(const float* __restrict__ latent, const float* __restrict__ w,
                           const float* __restrict__ b, __half* __restrict__ h0) {
    __shared__ float As[16][17];
    __shared__ float Ws[16][17];
    int tx = threadIdx.x, ty = threadIdx.y;
    int m = blockIdx.y * 16 + ty;
    int j = blockIdx.x * 16 + tx;
    float acc = 0.0f;
    for (int k0 = 0; k0 < 256; k0 += 16) {
        As[ty][tx] = latent[m * 256 + k0 + tx];
        Ws[ty][tx] = w[(blockIdx.x * 16 + ty) * 256 + k0 + tx];
        __syncthreads();
        #pragma unroll
        for (int kk = 0; kk < 16; kk++) acc += As[ty][kk] * Ws[tx][kk];
        __syncthreads();
    }
    h0[m * HID + j] = __float2half_rn(acc + b[j]);
}

// ---------------- fused FP16 GEMM + LSTM cell ----------------
// gates[B,4H] = A1@W1^T + A2@W2^T + bias (n interleaved: n'=4h+g, gates i,f,g,o)
// Tile 128x128, K-chunk 32 halfs, double-buffered cp.async, 8 warps (4m x 2n).
// smem: A[2][128][40]h (20480B) + B[2][128][40]h (20480B) = 40960B; row stride 80B
// gives conflict-free 32-bit fragment loads (banks (20r+q)%32 all distinct).
#define GEMM_SMEM_BYTES 40960

__global__ void __launch_bounds__(256, 2) gemm_lstm(
    const __half* __restrict__ A1, const __half* __restrict__ W1, int K1,
    const __half* __restrict__ A2, const __half* __restrict__ W2, int K2,
    const float* __restrict__ bias, float* __restrict__ c_state,
    __half* __restrict__ h_out) {
    extern __shared__ char sm[];

    const int tid  = threadIdx.x;
    const int bm   = blockIdx.y;     // M tile (batch)
    const int bn   = blockIdx.x;     // N tile (gate cols)
    const int lane = tid & 31, warp = tid >> 5;
    const int wm   = warp & 3, wn = warp >> 2;
    const int gid  = lane >> 2, qid = lane & 3;

    float acc[2][8][4];
    #pragma unroll
    for (int i = 0; i < 2; i++)
        #pragma unroll
        for (int j = 0; j < 8; j++)
            #pragma unroll
            for (int k = 0; k < 4; k++) acc[i][j][k] = 0.0f;

    // loader: 512 16B-chunks per operand per K-32 chunk; 2 per thread each.
    // chunk id c = tid + j*256 -> row = c>>2, q16 = c&3
    auto load_chunk = [&](const __half* Ab, const __half* Wb, int K, int ko, int buf) {
        char* Ad = sm + buf * 10240;
        char* Bd = sm + 20480 + buf * 10240;
        #pragma unroll
        for (int j = 0; j < 2; j++) {
            int c = tid + j * 256;
            int r = c >> 2, q16 = c & 3;
            cp16(Ad + r * 80 + q16 * 16, Ab + (size_t)r * K + ko + q16 * 8);
            cp16(Bd + r * 80 + q16 * 16, Wb + (size_t)r * K + ko + q16 * 8);
        }
        asm volatile("cp.async.commit_group;" ::: "memory");
    };

    int buf = 0;
    #pragma unroll 1
    for (int seg = 0; seg < 2; seg++) {
        const __half* Ab = (seg ? A2 : A1) + (size_t)bm * 128 * (seg ? K2 : K1);
        const __half* Wb = (seg ? W2 : W1) + (size_t)bn * 128 * (seg ? K2 : K1);
        const int K  = seg ? K2 : K1;
        const int nk = K >> 5;

        load_chunk(Ab, Wb, K, 0, buf);

        #pragma unroll 1
        for (int kt = 0; kt < nk; kt++) {
            if (kt + 1 < nk) {
                load_chunk(Ab, Wb, K, (kt + 1) << 5, buf ^ 1);
                asm volatile("cp.async.wait_group 1;" ::: "memory");
            } else {
                asm volatile("cp.async.wait_group 0;" ::: "memory");
            }
            __syncthreads();

            const char* Ac = sm + buf * 10240;
            const char* Bc = sm + 20480 + buf * 10240;
            #pragma unroll
            for (int k16 = 0; k16 < 32; k16 += 16) {
                const int koff = k16 * 2 + qid * 4;    // bytes within row
                uint32_t a[2][4];
                #pragma unroll
                for (int mf = 0; mf < 2; mf++) {
                    int r = wm * 32 + mf * 16 + gid;
                    a[mf][0] = *(const uint32_t*)(Ac + r * 80 + koff);
                    a[mf][1] = *(const uint32_t*)(Ac + (r + 8) * 80 + koff);
                    a[mf][2] = *(const uint32_t*)(Ac + r * 80 + koff + 16);
                    a[mf][3] = *(const uint32_t*)(Ac + (r + 8) * 80 + koff + 16);
                }
                uint32_t b[8][2];
                #pragma unroll
                for (int nf = 0; nf < 8; nf++) {
                    int n = wn * 64 + nf * 8 + gid;
                    b[nf][0] = *(const uint32_t*)(Bc + n * 80 + koff);
                    b[nf][1] = *(const uint32_t*)(Bc + n * 80 + koff + 16);
                }
                #pragma unroll
                for (int nf = 0; nf < 8; nf++) {
                    mma16(acc[0][nf], a[0][0], a[0][1], a[0][2], a[0][3],
                          b[nf][0], b[nf][1]);
                    mma16(acc[1][nf], a[1][0], a[1][1], a[1][2], a[1][3],
                          b[nf][0], b[nf][1]);
                }
            }
            __syncthreads();
            buf ^= 1;
        }
    }

    // -------- fused LSTM cell epilogue (smem reused; same as proven r7/r11) --------
    float* Cs    = (float*)sm;                 // [128][33]
    float* Hs    = Cs + 128 * 33;              // [128][33]
    float* Bbias = Cs + 2 * 128 * 33;          // [128]
    const int jbase = bn * 32;

    for (int e = tid; e < 128 * 32; e += 256) {
        int r = e >> 5, j = e & 31;
        Cs[r * 33 + j] = c_state[(size_t)(bm * 128 + r) * HID + jbase + j];
    }
    if (tid < 128) Bbias[tid] = bias[bn * 128 + tid];
    __syncthreads();

    #pragma unroll
    for (int mf = 0; mf < 2; mf++) {
        #pragma unroll
        for (int nf = 0; nf < 8; nf++) {
            int r  = wm * 32 + mf * 16 + gid;
            int cb = wn * 64 + nf * 8 + 2 * qid;
            float bv0 = Bbias[cb], bv1 = Bbias[cb + 1];
            float v0 = acc[mf][nf][0] + bv0;
            float v1 = acc[mf][nf][1] + bv1;
            float v2 = acc[mf][nf][2] + bv0;
            float v3 = acc[mf][nf][3] + bv1;
            // pair (i,f) lane with (g,o) lane
            float p0 = __shfl_xor_sync(0xffffffffu, v0, 1);
            float p1 = __shfl_xor_sync(0xffffffffu, v1, 1);
            float p2 = __shfl_xor_sync(0xffffffffu, v2, 1);
            float p3 = __shfl_xor_sync(0xffffffffu, v3, 1);
            if (!(qid & 1)) {
                int jl = wn * 16 + nf * 2 + (qid >> 1);
                {
                    float co = Cs[r * 33 + jl];
                    float cn = sigmoidf(v1) * co + sigmoidf(v0) * tanhf(p0);
                    float hn = sigmoidf(p1) * tanhf(cn);
                    Cs[r * 33 + jl] = cn;
                    Hs[r * 33 + jl] = hn;
                }
                {
                    float co = Cs[(r + 8) * 33 + jl];
                    float cn = sigmoidf(v3) * co + sigmoidf(v2) * tanhf(p2);
                    float hn = sigmoidf(p3) * tanhf(cn);
                    Cs[(r + 8) * 33 + jl] = cn;
                    Hs[(r + 8) * 33 + jl] = hn;
                }
            }
        }
    }
    __syncthreads();

    for (int e = tid; e < 128 * 32; e += 256) {
        int r = e >> 5, j = e & 31;
        size_t gix = (size_t)(bm * 128 + r) * HID + jbase + j;
        c_state[gix] = Cs[r * 33 + j];
        h_out[gix]   = __float2half_rn(Hs[r * 33 + j]);
    }
}

// ---------------- logits + softmax feedback ----------------
// 128 blocks x 256 threads; fc2_w (42x1024 fp32) staged in smem; warp handles 2 rows.
#define LOGITS_SMEM_BYTES ((VOC * HID + 16 * KP) * 4)

__global__ void __launch_bounds__(256) logits_kernel(
    const __half* __restrict__ h, const float* __restrict__ fc2_w,
    const float* __restrict__ fc2_b, float* __restrict__ out,
    __half* __restrict__ x, int t) {
    extern __shared__ float sw[];                 // [42*1024] weights
    float* ls = sw + VOC * HID;                   // [16][KP] logits stage
    const int tid = threadIdx.x;
    const int warp = tid >> 5, lane = tid & 31;

    float4* sw4 = (float4*)sw;
    const float4* gw4 = (const float4*)fc2_w;
    for (int i = tid; i < VOC * (HID / 4); i += 256) sw4[i] = gw4[i];
    __syncthreads();

    const int r0 = blockIdx.x * 16 + warp * 2;    // this warp: rows r0, r0+1
    const __half2* h2 = (const __half2*)h;        // 512 half2 per row
    float2 ha[16], hb[16];
    #pragma unroll
    for (int i = 0; i < 16; i++) {
        ha[i] = __half22float2(h2[(size_t)r0 * 512 + i * 32 + lane]);
        hb[i] = __half22float2(h2[(size_t)(r0 + 1) * 512 + i * 32 + lane]);
    }

    const float2* sw2 = (const float2*)sw;
    for (int v = 0; v < VOC; v++) {
        float sa = 0.0f, sb = 0.0f;
        #pragma unroll
        for (int i = 0; i < 16; i++) {
            float2 w2 = sw2[v * 512 + i * 32 + lane];
            sa += ha[i].x * w2.x + ha[i].y * w2.y;
            sb += hb[i].x * w2.x + hb[i].y * w2.y;
        }
        #pragma unroll
        for (int o = 16; o; o >>= 1) {
            sa += __shfl_xor_sync(0xffffffffu, sa, o);
            sb += __shfl_xor_sync(0xffffffffu, sb, o);
        }
        if (lane == 0) {
            float bv = fc2_b[v];
            float la = sa + bv, lb = sb + bv;
            ls[(warp * 2) * KP + v]     = la;
            ls[(warp * 2 + 1) * KP + v] = lb;
            out[((size_t)r0 * SEQ + t) * VOC + v]       = la;   // pre-softmax logits
            out[((size_t)(r0 + 1) * SEQ + t) * VOC + v] = lb;
        }
    }
    __syncwarp();

    #pragma unroll
    for (int rr = 0; rr < 2; rr++) {
        int r = r0 + rr;
        float v1 = (lane < VOC)      ? ls[(warp * 2 + rr) * KP + lane]      : -1e30f;
        float v2 = (lane + 32 < VOC) ? ls[(warp * 2 + rr) * KP + lane + 32] : -1e30f;
        float m = fmaxf(v1, v2);
        #pragma unroll
        for (int o = 16; o; o >>= 1) m = fmaxf(m, __shfl_xor_sync(0xffffffffu, m, o));
        float e1 = (lane < VOC)      ? expf(v1 - m) : 0.0f;
        float e2 = (lane + 32 < VOC) ? expf(v2 - m) : 0.0f;
        float s = e1 + e2;
        #pragma unroll
        for (int o = 16; o; o >>= 1) s += __shfl_xor_sync(0xffffffffu, s, o);
        float inv = 1.0f / s;
        if (lane < VOC)      x[(size_t)r * KP + lane]      = __float2half_rn(e1 * inv);
        if (lane + 32 < VOC) x[(size_t)r * KP + lane + 32] = __float2half_rn(e2 * inv);
    }
}

// ---------------- host ----------------
extern "C" void kernel_launch(void* const* d_in, const int* in_sizes, int n_in,
                              void* d_out, int out_size) {
    const float* latent = (const float*)d_in[0];
    const float* fc1_w  = (const float*)d_in[1];
    const float* fc1_b  = (const float*)d_in[2];
    const float* fc2_w  = (const float*)d_in[3];
    const float* fc2_b  = (const float*)d_in[4];
    const float* w_ih0  = (const float*)d_in[5];
    const float* w_hh0  = (const float*)d_in[6];
    const float* b_ih0  = (const float*)d_in[7];
    const float* b_hh0  = (const float*)d_in[8];
    const float* w_ih1  = (const float*)d_in[9];
    const float* w_hh1  = (const float*)d_in[10];
    const float* b_ih1  = (const float*)d_in[11];
    const float* b_hh1  = (const float*)d_in[12];
    float* out = (float*)d_out;

    __half *Whh0, *Wih1, *Whh1, *Wih0, *h0a, *h0b, *h1a, *h1b, *x;
    float *b0, *b1, *c0, *c1;
    cudaGetSymbolAddress((void**)&Whh0, g_Whh0);
    cudaGetSymbolAddress((void**)&Wih1, g_Wih1);
    cudaGetSymbolAddress((void**)&Whh1, g_Whh1);
    cudaGetSymbolAddress((void**)&Wih0, g_Wih0);
    cudaGetSymbolAddress((void**)&b0, g_b0);
    cudaGetSymbolAddress((void**)&b1, g_b1);
    cudaGetSymbolAddress((void**)&h0a, g_h0a);
    cudaGetSymbolAddress((void**)&h0b, g_h0b);
    cudaGetSymbolAddress((void**)&h1a, g_h1a);
    cudaGetSymbolAddress((void**)&h1b, g_h1b);
    cudaGetSymbolAddress((void**)&c0, g_c0);
    cudaGetSymbolAddress((void**)&c1, g_c1);
    cudaGetSymbolAddress((void**)&x, g_x);

    cudaFuncSetAttribute(logits_kernel, cudaFuncAttributeMaxDynamicSharedMemorySize,
                         LOGITS_SMEM_BYTES);
    cudaFuncSetAttribute(gemm_lstm, cudaFuncAttributeMaxDynamicSharedMemorySize,
                         GEMM_SMEM_BYTES);

    // exactly 5 prep launches (so ncu -s 5 -c 1 profiles the first gemm_lstm)
    pack_w3<<<dim3((NG * HID + 255) / 256, 3), 256>>>(w_hh0, w_ih1, w_hh1,
                                                      Whh0, Wih1, Whh1);
    pack_wih0<<<(NG * KP + 255) / 256, 256>>>(w_ih0, Wih0);
    prep_bias2<<<(NG + 255) / 256, 256>>>(b_ih0, b_hh0, b_ih1, b_hh1, b0, b1);
    init_states<<<(BATCH * HID + 255) / 256, 256>>>(h1a, c0, c1, x);
    fc1_kernel<<<dim3(HID / 16, BATCH / 16), dim3(16, 16)>>>(latent, fc1_w, fc1_b, h0a);

    __half* h0bufs[2] = {h0a, h0b};
    __half* h1bufs[2] = {h1a, h1b};
    dim3 ggrid(NG / 128, BATCH / 128);  // (32, 16)

    for (int t = 0; t < SEQ; t++) {
        __half* h0i = h0bufs[t & 1];
        __half* h0o = h0bufs[(t + 1) & 1];
        __half* h1i = h1bufs[t & 1];
        __half* h1o = h1bufs[(t + 1) & 1];
        // layer 0: gates = x@Wih0' + h0@Whh0' + b0 ; fused cell -> h0o, c0
        gemm_lstm<<<ggrid, 256, GEMM_SMEM_BYTES>>>(x, Wih0, KP, h0i, Whh0, HID,
                                                   b0, c0, h0o);
        // layer 1: gates = h0o@Wih1' + h1@Whh1' + b1 ; fused cell -> h1o, c1
        gemm_lstm<<<ggrid, 256, GEMM_SMEM_BYTES>>>(h0o, Wih1, HID, h1i, Whh1, HID,
                                                   b1, c1, h1o);
        // logits (written to out) + softmax feedback into x
        logits_kernel<<<BATCH / 16, 256, LOGITS_SMEM_BYTES>>>(h1o, fc2_w, fc2_b,
                                                              out, x, t);
    }
}